// round 8
// baseline (speedup 1.0000x reference)
#include <cuda_runtime.h>
#include <math.h>

#define NUM_USERS 60000
#define NUM_ITEMS 40000
#define NUM_NODES 100000
#define EMB 64
#define HID 32
#define N_EDGES 1600000
#define BATCH 16384

#define SCAN_BLK 1024
#define NB ((NUM_NODES + SCAN_BLK - 1) / SCAN_BLK)   // 98

#define ST_AGG  (1 << 30)
#define ST_INCL (2 << 30)
#define ST_VAL  0x3FFFFFFF

// ---------------- device scratch (allocation-free rule) ----------------
__device__ __align__(16) float g_h1[NUM_NODES * HID];   // lin1 output (32-dim)
__device__ __align__(16) float g_y[NUM_NODES * HID];    // relu(agg1)  (32-dim)
__device__ int   g_counts[NUM_NODES];                   // degree hist / cursor
__device__ int   g_row_ptr[NUM_NODES + 1];
__device__ int   g_tile_state[NB];                      // lookback-scan states
__device__ __align__(8) int2 g_epk[N_EDGES];            // (col, val-bits), CSR order

// ---------------------------------------------------------------------------
// lin1: h1[n][j] = feat[n].W1[j] + b1[j]. Also zeroes g_counts / g_tile_state.
__global__ void lin1_kernel(const float* __restrict__ uemb,
                            const float* __restrict__ iemb,
                            const float* __restrict__ W,
                            const float* __restrict__ b) {
    int gt = blockIdx.x * blockDim.x + threadIdx.x;
    for (int i = gt; i < NUM_NODES; i += gridDim.x * blockDim.x)
        g_counts[i] = 0;
    if (gt < NB) g_tile_state[gt] = 0;

    int lane = threadIdx.x & 31;
    float w[EMB];
#pragma unroll
    for (int k = 0; k < EMB; k++) w[k] = __ldg(&W[lane * EMB + k]);
    float bias = __ldg(&b[lane]);

    int warp   = blockIdx.x * (blockDim.x >> 5) + (threadIdx.x >> 5);
    int nwarps = gridDim.x * (blockDim.x >> 5);

    for (int node = warp; node < NUM_NODES; node += nwarps) {
        const float* feat = (node < NUM_USERS)
            ? uemb + (size_t)node * EMB
            : iemb + (size_t)(node - NUM_USERS) * EMB;
        float x0 = __ldg(&feat[lane]);
        float x1 = __ldg(&feat[lane + 32]);
        float acc = bias;
#pragma unroll
        for (int k = 0; k < 32; k++) {
            acc += __shfl_sync(0xffffffffu, x0, k) * w[k];
            acc += __shfl_sync(0xffffffffu, x1, k) * w[k + 32];
        }
        g_h1[(size_t)node * HID + lane] = acc;
    }
}

// ---------------------------------------------------------------------------
// degree histogram: 4 edges/thread, int4 load, fire-and-forget atomics (RED)
__global__ void hist_kernel(const int* __restrict__ rows) {
    int t = blockIdx.x * blockDim.x + threadIdx.x;
    int e4 = t * 4;
    if (e4 + 3 < N_EDGES) {
        int4 r4 = *(const int4*)(rows + e4);
        atomicAdd(&g_counts[r4.x], 1);
        atomicAdd(&g_counts[r4.y], 1);
        atomicAdd(&g_counts[r4.z], 1);
        atomicAdd(&g_counts[r4.w], 1);
    } else {
        for (int e = e4; e < N_EDGES; e++) atomicAdd(&g_counts[rows[e]], 1);
    }
}

// ---------------------------------------------------------------------------
// Single-pass exclusive scan (decoupled lookback), 98 blocks.
__global__ void scan_kernel() {
    __shared__ int sh[SCAN_BLK];
    __shared__ int s_prefix;
    int tid = threadIdx.x;
    int b = blockIdx.x;
    int i = b * SCAN_BLK + tid;
    int v = (i < NUM_NODES) ? g_counts[i] : 0;
    sh[tid] = v;
    __syncthreads();
#pragma unroll
    for (int off = 1; off < SCAN_BLK; off <<= 1) {
        int t = (tid >= off) ? sh[tid - off] : 0;
        __syncthreads();
        sh[tid] += t;
        __syncthreads();
    }
    int incl = sh[tid];
    int agg = sh[SCAN_BLK - 1];

    if (tid == 0) {
        int st = ((b == 0) ? ST_INCL : ST_AGG) | agg;
        atomicExch(&g_tile_state[b], st);
        if (b == 0) s_prefix = 0;
    }

    if (b > 0 && tid < 32) {
        int running = 0;
        int idx = b - 1;
        while (true) {
            int look = idx - tid;
            int st;
            if (look >= 0) {
                do { st = atomicAdd(&g_tile_state[look], 0); } while (st == 0);
            } else {
                st = ST_INCL;
            }
            int status = st & ~ST_VAL;
            int val    = st & ST_VAL;
            unsigned mask = __ballot_sync(0xffffffffu, status == ST_INCL);
            if (mask) {
                int first = __ffs(mask) - 1;
                int contrib = (tid <= first) ? val : 0;
#pragma unroll
                for (int o = 16; o > 0; o >>= 1)
                    contrib += __shfl_xor_sync(0xffffffffu, contrib, o);
                running += contrib;
                break;
            } else {
                int contrib = val;
#pragma unroll
                for (int o = 16; o > 0; o >>= 1)
                    contrib += __shfl_xor_sync(0xffffffffu, contrib, o);
                running += contrib;
                idx -= 32;
            }
        }
        if (tid == 0) {
            atomicExch(&g_tile_state[b], ST_INCL | (running + agg));
            s_prefix = running;
        }
    }
    __syncthreads();

    int prefix = s_prefix;
    if (i < NUM_NODES) {
        int excl = prefix + incl - v;
        g_row_ptr[i] = excl;
        g_counts[i]  = excl;          // cursor for permute
    }
    if (b == NB - 1 && tid == 0) g_row_ptr[NUM_NODES] = N_EDGES;
}

// ---------------------------------------------------------------------------
// CSR permute: 4 edges/thread, vector loads, 4 independent atomic->store chains
__global__ void permute_kernel(const int* __restrict__ rows,
                               const int* __restrict__ cols,
                               const float* __restrict__ vals) {
    int t = blockIdx.x * blockDim.x + threadIdx.x;
    int e4 = t * 4;
    if (e4 + 3 < N_EDGES) {
        int4   r4 = *(const int4*)(rows + e4);
        int4   c4 = *(const int4*)(cols + e4);
        float4 v4 = *(const float4*)(vals + e4);
        int p0 = atomicAdd(&g_counts[r4.x], 1);
        int p1 = atomicAdd(&g_counts[r4.y], 1);
        int p2 = atomicAdd(&g_counts[r4.z], 1);
        int p3 = atomicAdd(&g_counts[r4.w], 1);
        g_epk[p0] = make_int2(c4.x, __float_as_int(v4.x));
        g_epk[p1] = make_int2(c4.y, __float_as_int(v4.y));
        g_epk[p2] = make_int2(c4.z, __float_as_int(v4.z));
        g_epk[p3] = make_int2(c4.w, __float_as_int(v4.w));
    } else {
        for (int e = e4; e < N_EDGES; e++) {
            int pos = atomicAdd(&g_counts[rows[e]], 1);
            g_epk[pos] = make_int2(cols[e], __float_as_int(vals[e]));
        }
    }
}

// ---------------------------------------------------------------------------
// SpMM layer 1: y[r] = relu( sum_j v_j * h1[col_j] ).
// lane=(g,f): g edge subgroup (4 edges/iter), f float4 feature chunk.
// Next row's bounds prefetched before processing the current row.
__global__ void spmm1_kernel() {
    int lane = threadIdx.x & 31;
    int g = lane >> 3;
    int f = lane & 7;
    int warp   = blockIdx.x * (blockDim.x >> 5) + (threadIdx.x >> 5);
    int nwarps = gridDim.x * (blockDim.x >> 5);
    const float4* tbl = (const float4*)g_h1;

    int r = warp;
    int jb = 0, je = 0;
    if (r < NUM_NODES) { jb = __ldg(&g_row_ptr[r]); je = __ldg(&g_row_ptr[r + 1]); }
    while (r < NUM_NODES) {
        int rn = r + nwarps;
        int jbn = 0, jen = 0;
        if (rn < NUM_NODES) { jbn = __ldg(&g_row_ptr[rn]); jen = __ldg(&g_row_ptr[rn + 1]); }

        float4 acc = make_float4(0.f, 0.f, 0.f, 0.f);
#pragma unroll 4
        for (int j0 = jb; j0 < je; j0 += 4) {
            int j = j0 + g;
            bool act = (j < je);
            int2 cv = __ldg(&g_epk[act ? j : (je - 1)]);
            float v = act ? __int_as_float(cv.y) : 0.f;
            float4 h = __ldg(&tbl[(size_t)cv.x * 8 + f]);
            acc.x += v * h.x;
            acc.y += v * h.y;
            acc.z += v * h.z;
            acc.w += v * h.w;
        }
#pragma unroll
        for (int o = 8; o <= 16; o <<= 1) {
            acc.x += __shfl_xor_sync(0xffffffffu, acc.x, o);
            acc.y += __shfl_xor_sync(0xffffffffu, acc.y, o);
            acc.z += __shfl_xor_sync(0xffffffffu, acc.z, o);
            acc.w += __shfl_xor_sync(0xffffffffu, acc.w, o);
        }
        if (g == 0) {
            float4 yv = make_float4(fmaxf(acc.x, 0.f), fmaxf(acc.y, 0.f),
                                    fmaxf(acc.z, 0.f), fmaxf(acc.w, 0.f));
            ((float4*)g_y)[(size_t)r * 8 + f] = yv;
        }
        r = rn; jb = jbn; je = jen;
    }
}

// ---------------------------------------------------------------------------
// SpMM layer 2 + post-aggregation linear. W2 in shared for occupancy.
__global__ void spmm2_kernel(const float* __restrict__ W2,
                             const float* __restrict__ b2,
                             float* __restrict__ out_h2) {
    __shared__ float sW[HID][EMB];      // sW[k][o] = W2[o][k]
    int tid = threadIdx.x;
    for (int i = tid; i < EMB * HID; i += blockDim.x) {
        int o = i >> 5, k = i & 31;
        sW[k][o] = W2[i];
    }
    __syncthreads();

    int lane = tid & 31;
    int g = lane >> 3;
    int f = lane & 7;
    float b0 = __ldg(&b2[lane]);
    float b1 = __ldg(&b2[lane + 32]);

    int warp   = blockIdx.x * (blockDim.x >> 5) + (tid >> 5);
    int nwarps = gridDim.x * (blockDim.x >> 5);
    const float4* tbl = (const float4*)g_y;

    int r = warp;
    int jb = 0, je = 0;
    if (r < NUM_NODES) { jb = __ldg(&g_row_ptr[r]); je = __ldg(&g_row_ptr[r + 1]); }
    while (r < NUM_NODES) {
        int rn = r + nwarps;
        int jbn = 0, jen = 0;
        if (rn < NUM_NODES) { jbn = __ldg(&g_row_ptr[rn]); jen = __ldg(&g_row_ptr[rn + 1]); }

        float4 acc = make_float4(0.f, 0.f, 0.f, 0.f);
        float s = 0.f;
#pragma unroll 4
        for (int j0 = jb; j0 < je; j0 += 4) {
            int j = j0 + g;
            bool act = (j < je);
            int2 cv = __ldg(&g_epk[act ? j : (je - 1)]);
            float v = act ? __int_as_float(cv.y) : 0.f;
            float4 h = __ldg(&tbl[(size_t)cv.x * 8 + f]);
            acc.x += v * h.x;
            acc.y += v * h.y;
            acc.z += v * h.z;
            acc.w += v * h.w;
            s += v;
        }
#pragma unroll
        for (int o = 8; o <= 16; o <<= 1) {
            acc.x += __shfl_xor_sync(0xffffffffu, acc.x, o);
            acc.y += __shfl_xor_sync(0xffffffffu, acc.y, o);
            acc.z += __shfl_xor_sync(0xffffffffu, acc.z, o);
            acc.w += __shfl_xor_sync(0xffffffffu, acc.w, o);
            s     += __shfl_xor_sync(0xffffffffu, s, o);
        }
        float xs0 = acc.x, xs1 = acc.y, xs2 = acc.z, xs3 = acc.w;
        float o0 = s * b0, o1 = s * b1;
#pragma unroll
        for (int k = 0; k < 32; k++) {
            int src = k >> 2;
            float xk;
            switch (k & 3) {
                case 0: xk = __shfl_sync(0xffffffffu, xs0, src); break;
                case 1: xk = __shfl_sync(0xffffffffu, xs1, src); break;
                case 2: xk = __shfl_sync(0xffffffffu, xs2, src); break;
                default: xk = __shfl_sync(0xffffffffu, xs3, src); break;
            }
            o0 += xk * sW[k][lane];
            o1 += xk * sW[k][lane + 32];
        }
        out_h2[(size_t)r * EMB + lane]      = fmaxf(o0, 0.f);
        out_h2[(size_t)r * EMB + lane + 32] = fmaxf(o1, 0.f);
        r = rn; jb = jbn; je = jen;
    }
}

// ---------------------------------------------------------------------------
// prediction MLP. warp per batch sample; lane = hidden unit
__global__ void predict_kernel(const int* __restrict__ uid,
                               const int* __restrict__ iid,
                               const float* __restrict__ h2,
                               const float* __restrict__ p1w,
                               const float* __restrict__ p1b,
                               const float* __restrict__ p2w,
                               const float* __restrict__ p2b,
                               float* __restrict__ scores) {
    int lane = threadIdx.x & 31;
    float w[2 * EMB];
#pragma unroll
    for (int k = 0; k < 2 * EMB; k++) w[k] = __ldg(&p1w[lane * 2 * EMB + k]);
    float bias = __ldg(&p1b[lane]);
    float w2   = __ldg(&p2w[lane]);
    float b2v  = __ldg(&p2b[0]);

    int warp   = blockIdx.x * (blockDim.x >> 5) + (threadIdx.x >> 5);
    int nwarps = gridDim.x * (blockDim.x >> 5);

    for (int s = warp; s < BATCH; s += nwarps) {
        int u  = __ldg(&uid[s]);
        int it = __ldg(&iid[s]);
        const float* bu = h2 + (size_t)u * EMB;
        const float* bi = h2 + (size_t)(NUM_USERS + it) * EMB;
        float x0 = bu[lane], x1 = bu[lane + 32];
        float x2 = bi[lane], x3 = bi[lane + 32];
        float acc = bias;
#pragma unroll
        for (int k = 0; k < 32; k++) {
            acc += __shfl_sync(0xffffffffu, x0, k) * w[k];
            acc += __shfl_sync(0xffffffffu, x1, k) * w[k + 32];
            acc += __shfl_sync(0xffffffffu, x2, k) * w[k + 64];
            acc += __shfl_sync(0xffffffffu, x3, k) * w[k + 96];
        }
        float z = fmaxf(acc, 0.f) * w2;
#pragma unroll
        for (int o = 16; o > 0; o >>= 1)
            z += __shfl_xor_sync(0xffffffffu, z, o);
        if (lane == 0)
            scores[s] = 1.f / (1.f + expf(-(z + b2v)));
    }
}

// ---------------------------------------------------------------------------
extern "C" void kernel_launch(void* const* d_in, const int* in_sizes, int n_in,
                              void* d_out, int out_size) {
    const int*   user_ids = (const int*)d_in[0];
    const int*   item_ids = (const int*)d_in[1];
    const int*   adj_rows = (const int*)d_in[2];
    const int*   adj_cols = (const int*)d_in[3];
    const float* adj_vals = (const float*)d_in[4];
    const float* uemb     = (const float*)d_in[5];
    const float* iemb     = (const float*)d_in[6];
    const float* gc1w     = (const float*)d_in[7];
    const float* gc1b     = (const float*)d_in[8];
    const float* gc2w     = (const float*)d_in[9];
    const float* gc2b     = (const float*)d_in[10];
    const float* p1w      = (const float*)d_in[11];
    const float* p1b      = (const float*)d_in[12];
    const float* p2w      = (const float*)d_in[13];
    const float* p2b      = (const float*)d_in[14];

    float* out    = (float*)d_out;
    float* out_h2 = out + BATCH;   // [NUM_NODES*EMB] = concat(user_emb, item_emb)

    const int TB = 256;
    const int E4 = (N_EDGES / 4 + TB - 1) / TB;   // 4-edge/thread grids

    // 1: lin1 + zero counts/tile-states
    lin1_kernel<<<592, TB>>>(uemb, iemb, gc1w, gc1b);
    // 2: degree histogram (4 edges/thread)
    hist_kernel<<<E4, TB>>>(adj_rows);
    // 3: single-pass lookback scan -> row_ptr + cursor
    scan_kernel<<<NB, SCAN_BLK>>>();
    // 4: CSR permute (4 edges/thread)
    permute_kernel<<<E4, TB>>>(adj_rows, adj_cols, adj_vals);
    // 5: layer-1 aggregate + ReLU
    spmm1_kernel<<<1184, TB>>>();
    // 6: layer-2 aggregate + lin2 + ReLU -> d_out
    spmm2_kernel<<<1184, TB>>>(gc2w, gc2b, out_h2);
    // 7: prediction head
    predict_kernel<<<148, TB>>>(user_ids, item_ids, out_h2,
                                p1w, p1b, p2w, p2b, out);
}

// round 9
// speedup vs baseline: 1.0058x; 1.0058x over previous
#include <cuda_runtime.h>
#include <math.h>

#define NUM_USERS 60000
#define NUM_ITEMS 40000
#define NUM_NODES 100000
#define EMB 64
#define HID 32
#define N_EDGES 1600000
#define BATCH 16384

#define SCAN_BLK 1024
#define NB ((NUM_NODES + SCAN_BLK - 1) / SCAN_BLK)   // 98

#define ST_AGG  (1 << 30)
#define ST_INCL (2 << 30)
#define ST_VAL  0x3FFFFFFF

// ---------------- device scratch (allocation-free rule) ----------------
__device__ __align__(16) float g_h1[NUM_NODES * HID];   // lin1 output (32-dim)
__device__ __align__(16) float g_y[NUM_NODES * HID];    // relu(agg1)  (32-dim)
__device__ int   g_counts[NUM_NODES];                   // degree hist / cursor
__device__ int   g_row_ptr[NUM_NODES + 1];
__device__ int   g_tile_state[NB];                      // lookback-scan states
__device__ __align__(8) int2 g_epk[N_EDGES];            // (col, val-bits), CSR order

// ---------------------------------------------------------------------------
// lin1: h1[n][j] = feat[n].W1[j] + b1[j]. Also zeroes g_counts / g_tile_state.
__global__ void lin1_kernel(const float* __restrict__ uemb,
                            const float* __restrict__ iemb,
                            const float* __restrict__ W,
                            const float* __restrict__ b) {
    int gt = blockIdx.x * blockDim.x + threadIdx.x;
    for (int i = gt; i < NUM_NODES; i += gridDim.x * blockDim.x)
        g_counts[i] = 0;
    if (gt < NB) g_tile_state[gt] = 0;

    int lane = threadIdx.x & 31;
    float w[EMB];
#pragma unroll
    for (int k = 0; k < EMB; k++) w[k] = __ldg(&W[lane * EMB + k]);
    float bias = __ldg(&b[lane]);

    int warp   = blockIdx.x * (blockDim.x >> 5) + (threadIdx.x >> 5);
    int nwarps = gridDim.x * (blockDim.x >> 5);

    for (int node = warp; node < NUM_NODES; node += nwarps) {
        const float* feat = (node < NUM_USERS)
            ? uemb + (size_t)node * EMB
            : iemb + (size_t)(node - NUM_USERS) * EMB;
        float x0 = __ldg(&feat[lane]);
        float x1 = __ldg(&feat[lane + 32]);
        float acc = bias;
#pragma unroll
        for (int k = 0; k < 32; k++) {
            acc += __shfl_sync(0xffffffffu, x0, k) * w[k];
            acc += __shfl_sync(0xffffffffu, x1, k) * w[k + 32];
        }
        g_h1[(size_t)node * HID + lane] = acc;
    }
}

// ---------------------------------------------------------------------------
// degree histogram: 4 edges/thread, int4 load, fire-and-forget atomics (RED)
__global__ void hist_kernel(const int* __restrict__ rows) {
    int t = blockIdx.x * blockDim.x + threadIdx.x;
    int e4 = t * 4;
    if (e4 + 3 < N_EDGES) {
        int4 r4 = *(const int4*)(rows + e4);
        atomicAdd(&g_counts[r4.x], 1);
        atomicAdd(&g_counts[r4.y], 1);
        atomicAdd(&g_counts[r4.z], 1);
        atomicAdd(&g_counts[r4.w], 1);
    } else {
        for (int e = e4; e < N_EDGES; e++) atomicAdd(&g_counts[rows[e]], 1);
    }
}

// ---------------------------------------------------------------------------
// Single-pass exclusive scan (decoupled lookback), 98 blocks.
__global__ void scan_kernel() {
    __shared__ int sh[SCAN_BLK];
    __shared__ int s_prefix;
    int tid = threadIdx.x;
    int b = blockIdx.x;
    int i = b * SCAN_BLK + tid;
    int v = (i < NUM_NODES) ? g_counts[i] : 0;
    sh[tid] = v;
    __syncthreads();
#pragma unroll
    for (int off = 1; off < SCAN_BLK; off <<= 1) {
        int t = (tid >= off) ? sh[tid - off] : 0;
        __syncthreads();
        sh[tid] += t;
        __syncthreads();
    }
    int incl = sh[tid];
    int agg = sh[SCAN_BLK - 1];

    if (tid == 0) {
        int st = ((b == 0) ? ST_INCL : ST_AGG) | agg;
        atomicExch(&g_tile_state[b], st);
        if (b == 0) s_prefix = 0;
    }

    if (b > 0 && tid < 32) {
        int running = 0;
        int idx = b - 1;
        while (true) {
            int look = idx - tid;
            int st;
            if (look >= 0) {
                do { st = atomicAdd(&g_tile_state[look], 0); } while (st == 0);
            } else {
                st = ST_INCL;
            }
            int status = st & ~ST_VAL;
            int val    = st & ST_VAL;
            unsigned mask = __ballot_sync(0xffffffffu, status == ST_INCL);
            if (mask) {
                int first = __ffs(mask) - 1;
                int contrib = (tid <= first) ? val : 0;
#pragma unroll
                for (int o = 16; o > 0; o >>= 1)
                    contrib += __shfl_xor_sync(0xffffffffu, contrib, o);
                running += contrib;
                break;
            } else {
                int contrib = val;
#pragma unroll
                for (int o = 16; o > 0; o >>= 1)
                    contrib += __shfl_xor_sync(0xffffffffu, contrib, o);
                running += contrib;
                idx -= 32;
            }
        }
        if (tid == 0) {
            atomicExch(&g_tile_state[b], ST_INCL | (running + agg));
            s_prefix = running;
        }
    }
    __syncthreads();

    int prefix = s_prefix;
    if (i < NUM_NODES) {
        int excl = prefix + incl - v;
        g_row_ptr[i] = excl;
        g_counts[i]  = excl;          // cursor for permute
    }
    if (b == NB - 1 && tid == 0) g_row_ptr[NUM_NODES] = N_EDGES;
}

// ---------------------------------------------------------------------------
// CSR permute: 4 edges/thread, vector loads, 4 independent atomic->store chains
__global__ void permute_kernel(const int* __restrict__ rows,
                               const int* __restrict__ cols,
                               const float* __restrict__ vals) {
    int t = blockIdx.x * blockDim.x + threadIdx.x;
    int e4 = t * 4;
    if (e4 + 3 < N_EDGES) {
        int4   r4 = *(const int4*)(rows + e4);
        int4   c4 = *(const int4*)(cols + e4);
        float4 v4 = *(const float4*)(vals + e4);
        int p0 = atomicAdd(&g_counts[r4.x], 1);
        int p1 = atomicAdd(&g_counts[r4.y], 1);
        int p2 = atomicAdd(&g_counts[r4.z], 1);
        int p3 = atomicAdd(&g_counts[r4.w], 1);
        g_epk[p0] = make_int2(c4.x, __float_as_int(v4.x));
        g_epk[p1] = make_int2(c4.y, __float_as_int(v4.y));
        g_epk[p2] = make_int2(c4.z, __float_as_int(v4.z));
        g_epk[p3] = make_int2(c4.w, __float_as_int(v4.w));
    } else {
        for (int e = e4; e < N_EDGES; e++) {
            int pos = atomicAdd(&g_counts[rows[e]], 1);
            g_epk[pos] = make_int2(cols[e], __float_as_int(vals[e]));
        }
    }
}

// ---------------------------------------------------------------------------
// SpMM layer 1: y[r] = relu( sum_j v_j * h1[col_j] ).
// lane=(g,f): g edge subgroup (4 edges/iter), f float4 feature chunk.
// Next row's bounds prefetched before processing the current row.
__global__ void spmm1_kernel() {
    int lane = threadIdx.x & 31;
    int g = lane >> 3;
    int f = lane & 7;
    int warp   = blockIdx.x * (blockDim.x >> 5) + (threadIdx.x >> 5);
    int nwarps = gridDim.x * (blockDim.x >> 5);
    const float4* tbl = (const float4*)g_h1;

    int r = warp;
    int jb = 0, je = 0;
    if (r < NUM_NODES) { jb = __ldg(&g_row_ptr[r]); je = __ldg(&g_row_ptr[r + 1]); }
    while (r < NUM_NODES) {
        int rn = r + nwarps;
        int jbn = 0, jen = 0;
        if (rn < NUM_NODES) { jbn = __ldg(&g_row_ptr[rn]); jen = __ldg(&g_row_ptr[rn + 1]); }

        float4 acc = make_float4(0.f, 0.f, 0.f, 0.f);
#pragma unroll 4
        for (int j0 = jb; j0 < je; j0 += 4) {
            int j = j0 + g;
            bool act = (j < je);
            int2 cv = __ldg(&g_epk[act ? j : (je - 1)]);
            float v = act ? __int_as_float(cv.y) : 0.f;
            float4 h = __ldg(&tbl[(size_t)cv.x * 8 + f]);
            acc.x += v * h.x;
            acc.y += v * h.y;
            acc.z += v * h.z;
            acc.w += v * h.w;
        }
#pragma unroll
        for (int o = 8; o <= 16; o <<= 1) {
            acc.x += __shfl_xor_sync(0xffffffffu, acc.x, o);
            acc.y += __shfl_xor_sync(0xffffffffu, acc.y, o);
            acc.z += __shfl_xor_sync(0xffffffffu, acc.z, o);
            acc.w += __shfl_xor_sync(0xffffffffu, acc.w, o);
        }
        if (g == 0) {
            float4 yv = make_float4(fmaxf(acc.x, 0.f), fmaxf(acc.y, 0.f),
                                    fmaxf(acc.z, 0.f), fmaxf(acc.w, 0.f));
            ((float4*)g_y)[(size_t)r * 8 + f] = yv;
        }
        r = rn; jb = jbn; je = jen;
    }
}

// ---------------------------------------------------------------------------
// SpMM layer 2 + post-aggregation linear. W2 in shared for occupancy.
__global__ void spmm2_kernel(const float* __restrict__ W2,
                             const float* __restrict__ b2,
                             float* __restrict__ out_h2) {
    __shared__ float sW[HID][EMB];      // sW[k][o] = W2[o][k]
    int tid = threadIdx.x;
    for (int i = tid; i < EMB * HID; i += blockDim.x) {
        int o = i >> 5, k = i & 31;
        sW[k][o] = W2[i];
    }
    __syncthreads();

    int lane = tid & 31;
    int g = lane >> 3;
    int f = lane & 7;
    float b0 = __ldg(&b2[lane]);
    float b1 = __ldg(&b2[lane + 32]);

    int warp   = blockIdx.x * (blockDim.x >> 5) + (tid >> 5);
    int nwarps = gridDim.x * (blockDim.x >> 5);
    const float4* tbl = (const float4*)g_y;

    int r = warp;
    int jb = 0, je = 0;
    if (r < NUM_NODES) { jb = __ldg(&g_row_ptr[r]); je = __ldg(&g_row_ptr[r + 1]); }
    while (r < NUM_NODES) {
        int rn = r + nwarps;
        int jbn = 0, jen = 0;
        if (rn < NUM_NODES) { jbn = __ldg(&g_row_ptr[rn]); jen = __ldg(&g_row_ptr[rn + 1]); }

        float4 acc = make_float4(0.f, 0.f, 0.f, 0.f);
        float s = 0.f;
#pragma unroll 4
        for (int j0 = jb; j0 < je; j0 += 4) {
            int j = j0 + g;
            bool act = (j < je);
            int2 cv = __ldg(&g_epk[act ? j : (je - 1)]);
            float v = act ? __int_as_float(cv.y) : 0.f;
            float4 h = __ldg(&tbl[(size_t)cv.x * 8 + f]);
            acc.x += v * h.x;
            acc.y += v * h.y;
            acc.z += v * h.z;
            acc.w += v * h.w;
            s += v;
        }
#pragma unroll
        for (int o = 8; o <= 16; o <<= 1) {
            acc.x += __shfl_xor_sync(0xffffffffu, acc.x, o);
            acc.y += __shfl_xor_sync(0xffffffffu, acc.y, o);
            acc.z += __shfl_xor_sync(0xffffffffu, acc.z, o);
            acc.w += __shfl_xor_sync(0xffffffffu, acc.w, o);
            s     += __shfl_xor_sync(0xffffffffu, s, o);
        }
        float xs0 = acc.x, xs1 = acc.y, xs2 = acc.z, xs3 = acc.w;
        float o0 = s * b0, o1 = s * b1;
#pragma unroll
        for (int k = 0; k < 32; k++) {
            int src = k >> 2;
            float xk;
            switch (k & 3) {
                case 0: xk = __shfl_sync(0xffffffffu, xs0, src); break;
                case 1: xk = __shfl_sync(0xffffffffu, xs1, src); break;
                case 2: xk = __shfl_sync(0xffffffffu, xs2, src); break;
                default: xk = __shfl_sync(0xffffffffu, xs3, src); break;
            }
            o0 += xk * sW[k][lane];
            o1 += xk * sW[k][lane + 32];
        }
        out_h2[(size_t)r * EMB + lane]      = fmaxf(o0, 0.f);
        out_h2[(size_t)r * EMB + lane + 32] = fmaxf(o1, 0.f);
        r = rn; jb = jbn; je = jen;
    }
}

// ---------------------------------------------------------------------------
// prediction MLP. warp per batch sample; lane = hidden unit
__global__ void predict_kernel(const int* __restrict__ uid,
                               const int* __restrict__ iid,
                               const float* __restrict__ h2,
                               const float* __restrict__ p1w,
                               const float* __restrict__ p1b,
                               const float* __restrict__ p2w,
                               const float* __restrict__ p2b,
                               float* __restrict__ scores) {
    int lane = threadIdx.x & 31;
    float w[2 * EMB];
#pragma unroll
    for (int k = 0; k < 2 * EMB; k++) w[k] = __ldg(&p1w[lane * 2 * EMB + k]);
    float bias = __ldg(&p1b[lane]);
    float w2   = __ldg(&p2w[lane]);
    float b2v  = __ldg(&p2b[0]);

    int warp   = blockIdx.x * (blockDim.x >> 5) + (threadIdx.x >> 5);
    int nwarps = gridDim.x * (blockDim.x >> 5);

    for (int s = warp; s < BATCH; s += nwarps) {
        int u  = __ldg(&uid[s]);
        int it = __ldg(&iid[s]);
        const float* bu = h2 + (size_t)u * EMB;
        const float* bi = h2 + (size_t)(NUM_USERS + it) * EMB;
        float x0 = bu[lane], x1 = bu[lane + 32];
        float x2 = bi[lane], x3 = bi[lane + 32];
        float acc = bias;
#pragma unroll
        for (int k = 0; k < 32; k++) {
            acc += __shfl_sync(0xffffffffu, x0, k) * w[k];
            acc += __shfl_sync(0xffffffffu, x1, k) * w[k + 32];
            acc += __shfl_sync(0xffffffffu, x2, k) * w[k + 64];
            acc += __shfl_sync(0xffffffffu, x3, k) * w[k + 96];
        }
        float z = fmaxf(acc, 0.f) * w2;
#pragma unroll
        for (int o = 16; o > 0; o >>= 1)
            z += __shfl_xor_sync(0xffffffffu, z, o);
        if (lane == 0)
            scores[s] = 1.f / (1.f + expf(-(z + b2v)));
    }
}

// ---------------------------------------------------------------------------
extern "C" void kernel_launch(void* const* d_in, const int* in_sizes, int n_in,
                              void* d_out, int out_size) {
    const int*   user_ids = (const int*)d_in[0];
    const int*   item_ids = (const int*)d_in[1];
    const int*   adj_rows = (const int*)d_in[2];
    const int*   adj_cols = (const int*)d_in[3];
    const float* adj_vals = (const float*)d_in[4];
    const float* uemb     = (const float*)d_in[5];
    const float* iemb     = (const float*)d_in[6];
    const float* gc1w     = (const float*)d_in[7];
    const float* gc1b     = (const float*)d_in[8];
    const float* gc2w     = (const float*)d_in[9];
    const float* gc2b     = (const float*)d_in[10];
    const float* p1w      = (const float*)d_in[11];
    const float* p1b      = (const float*)d_in[12];
    const float* p2w      = (const float*)d_in[13];
    const float* p2b      = (const float*)d_in[14];

    float* out    = (float*)d_out;
    float* out_h2 = out + BATCH;   // [NUM_NODES*EMB] = concat(user_emb, item_emb)

    const int TB = 256;
    const int E4 = (N_EDGES / 4 + TB - 1) / TB;   // 4-edge/thread grids

    // 1: lin1 + zero counts/tile-states
    lin1_kernel<<<592, TB>>>(uemb, iemb, gc1w, gc1b);
    // 2: degree histogram (4 edges/thread)
    hist_kernel<<<E4, TB>>>(adj_rows);
    // 3: single-pass lookback scan -> row_ptr + cursor
    scan_kernel<<<NB, SCAN_BLK>>>();
    // 4: CSR permute (4 edges/thread)
    permute_kernel<<<E4, TB>>>(adj_rows, adj_cols, adj_vals);
    // 5: layer-1 aggregate + ReLU
    spmm1_kernel<<<1184, TB>>>();
    // 6: layer-2 aggregate + lin2 + ReLU -> d_out
    spmm2_kernel<<<1184, TB>>>(gc2w, gc2b, out_h2);
    // 7: prediction head
    predict_kernel<<<148, TB>>>(user_ids, item_ids, out_h2,
                                p1w, p1b, p2w, p2b, out);
}

// round 10
// speedup vs baseline: 1.0361x; 1.0301x over previous
#include <cuda_runtime.h>
#include <cuda_fp16.h>
#include <math.h>

#define NUM_USERS 60000
#define NUM_ITEMS 40000
#define NUM_NODES 100000
#define EMB 64
#define HID 32
#define N_EDGES 1600000
#define BATCH 16384

#define SCAN_BLK 1024
#define NB ((NUM_NODES + SCAN_BLK - 1) / SCAN_BLK)   // 98

#define ST_AGG  (1 << 30)
#define ST_INCL (2 << 30)
#define ST_VAL  0x3FFFFFFF

// ---------------- device scratch (allocation-free rule) ----------------
__device__ __align__(16) __half g_h1h[NUM_NODES * HID];  // lin1 output, fp16 (64B/row)
__device__ __align__(16) __half g_yh[NUM_NODES * HID];   // relu(agg1), fp16 (64B/row)
__device__ int   g_counts[NUM_NODES];                    // degree hist / cursor
__device__ int   g_row_ptr[NUM_NODES + 1];
__device__ int   g_tile_state[NB];                       // lookback-scan states
__device__ __align__(8) int2 g_epk[N_EDGES];             // (col, val-bits), CSR order

// ---------------------------------------------------------------------------
// lin1: h1[n][j] = feat[n].W1[j] + b1[j]  -> fp16 table. Also zeroes counts.
__global__ void lin1_kernel(const float* __restrict__ uemb,
                            const float* __restrict__ iemb,
                            const float* __restrict__ W,
                            const float* __restrict__ b) {
    int gt = blockIdx.x * blockDim.x + threadIdx.x;
    for (int i = gt; i < NUM_NODES; i += gridDim.x * blockDim.x)
        g_counts[i] = 0;
    if (gt < NB) g_tile_state[gt] = 0;

    int lane = threadIdx.x & 31;
    float w[EMB];
#pragma unroll
    for (int k = 0; k < EMB; k++) w[k] = __ldg(&W[lane * EMB + k]);
    float bias = __ldg(&b[lane]);

    int warp   = blockIdx.x * (blockDim.x >> 5) + (threadIdx.x >> 5);
    int nwarps = gridDim.x * (blockDim.x >> 5);

    for (int node = warp; node < NUM_NODES; node += nwarps) {
        const float* feat = (node < NUM_USERS)
            ? uemb + (size_t)node * EMB
            : iemb + (size_t)(node - NUM_USERS) * EMB;
        float x0 = __ldg(&feat[lane]);
        float x1 = __ldg(&feat[lane + 32]);
        float acc = bias;
#pragma unroll
        for (int k = 0; k < 32; k++) {
            acc += __shfl_sync(0xffffffffu, x0, k) * w[k];
            acc += __shfl_sync(0xffffffffu, x1, k) * w[k + 32];
        }
        g_h1h[(size_t)node * HID + lane] = __float2half_rn(acc);
    }
}

// ---------------------------------------------------------------------------
// degree histogram: 4 edges/thread
__global__ void hist_kernel(const int* __restrict__ rows) {
    int t = blockIdx.x * blockDim.x + threadIdx.x;
    int e4 = t * 4;
    if (e4 + 3 < N_EDGES) {
        int4 r4 = *(const int4*)(rows + e4);
        atomicAdd(&g_counts[r4.x], 1);
        atomicAdd(&g_counts[r4.y], 1);
        atomicAdd(&g_counts[r4.z], 1);
        atomicAdd(&g_counts[r4.w], 1);
    } else {
        for (int e = e4; e < N_EDGES; e++) atomicAdd(&g_counts[rows[e]], 1);
    }
}

// ---------------------------------------------------------------------------
// Single-pass exclusive scan (decoupled lookback), 98 blocks.
__global__ void scan_kernel() {
    __shared__ int sh[SCAN_BLK];
    __shared__ int s_prefix;
    int tid = threadIdx.x;
    int b = blockIdx.x;
    int i = b * SCAN_BLK + tid;
    int v = (i < NUM_NODES) ? g_counts[i] : 0;
    sh[tid] = v;
    __syncthreads();
#pragma unroll
    for (int off = 1; off < SCAN_BLK; off <<= 1) {
        int t = (tid >= off) ? sh[tid - off] : 0;
        __syncthreads();
        sh[tid] += t;
        __syncthreads();
    }
    int incl = sh[tid];
    int agg = sh[SCAN_BLK - 1];

    if (tid == 0) {
        int st = ((b == 0) ? ST_INCL : ST_AGG) | agg;
        atomicExch(&g_tile_state[b], st);
        if (b == 0) s_prefix = 0;
    }

    if (b > 0 && tid < 32) {
        int running = 0;
        int idx = b - 1;
        while (true) {
            int look = idx - tid;
            int st;
            if (look >= 0) {
                do { st = atomicAdd(&g_tile_state[look], 0); } while (st == 0);
            } else {
                st = ST_INCL;
            }
            int status = st & ~ST_VAL;
            int val    = st & ST_VAL;
            unsigned mask = __ballot_sync(0xffffffffu, status == ST_INCL);
            if (mask) {
                int first = __ffs(mask) - 1;
                int contrib = (tid <= first) ? val : 0;
#pragma unroll
                for (int o = 16; o > 0; o >>= 1)
                    contrib += __shfl_xor_sync(0xffffffffu, contrib, o);
                running += contrib;
                break;
            } else {
                int contrib = val;
#pragma unroll
                for (int o = 16; o > 0; o >>= 1)
                    contrib += __shfl_xor_sync(0xffffffffu, contrib, o);
                running += contrib;
                idx -= 32;
            }
        }
        if (tid == 0) {
            atomicExch(&g_tile_state[b], ST_INCL | (running + agg));
            s_prefix = running;
        }
    }
    __syncthreads();

    int prefix = s_prefix;
    if (i < NUM_NODES) {
        int excl = prefix + incl - v;
        g_row_ptr[i] = excl;
        g_counts[i]  = excl;          // cursor for permute
    }
    if (b == NB - 1 && tid == 0) g_row_ptr[NUM_NODES] = N_EDGES;
}

// ---------------------------------------------------------------------------
// CSR permute: 4 edges/thread
__global__ void permute_kernel(const int* __restrict__ rows,
                               const int* __restrict__ cols,
                               const float* __restrict__ vals) {
    int t = blockIdx.x * blockDim.x + threadIdx.x;
    int e4 = t * 4;
    if (e4 + 3 < N_EDGES) {
        int4   r4 = *(const int4*)(rows + e4);
        int4   c4 = *(const int4*)(cols + e4);
        float4 v4 = *(const float4*)(vals + e4);
        int p0 = atomicAdd(&g_counts[r4.x], 1);
        int p1 = atomicAdd(&g_counts[r4.y], 1);
        int p2 = atomicAdd(&g_counts[r4.z], 1);
        int p3 = atomicAdd(&g_counts[r4.w], 1);
        g_epk[p0] = make_int2(c4.x, __float_as_int(v4.x));
        g_epk[p1] = make_int2(c4.y, __float_as_int(v4.y));
        g_epk[p2] = make_int2(c4.z, __float_as_int(v4.z));
        g_epk[p3] = make_int2(c4.w, __float_as_int(v4.w));
    } else {
        for (int e = e4; e < N_EDGES; e++) {
            int pos = atomicAdd(&g_counts[rows[e]], 1);
            g_epk[pos] = make_int2(cols[e], __float_as_int(vals[e]));
        }
    }
}

// ---------------------------------------------------------------------------
// SpMM layer 1: y[r] = relu( sum_j v_j * h1[col_j] ), fp16 table, fp32 acc.
// lane=(g,f): f=lane&3 -> 16B chunk (8 halves) of the 64B row; g=lane>>2 ->
// 8 edges per iteration. Same-f lanes are xor{4,8,16} apart.
__global__ void spmm1_kernel() {
    int lane = threadIdx.x & 31;
    int f = lane & 3;
    int g = lane >> 2;
    int warp   = blockIdx.x * (blockDim.x >> 5) + (threadIdx.x >> 5);
    int nwarps = gridDim.x * (blockDim.x >> 5);
    const uint4* tbl = (const uint4*)g_h1h;   // 4 × uint4 per row

    int r = warp;
    int jb = 0, je = 0;
    if (r < NUM_NODES) { jb = __ldg(&g_row_ptr[r]); je = __ldg(&g_row_ptr[r + 1]); }
    while (r < NUM_NODES) {
        int rn = r + nwarps;
        int jbn = 0, jen = 0;
        if (rn < NUM_NODES) { jbn = __ldg(&g_row_ptr[rn]); jen = __ldg(&g_row_ptr[rn + 1]); }

        float acc[8];
#pragma unroll
        for (int i = 0; i < 8; i++) acc[i] = 0.f;

#pragma unroll 2
        for (int j0 = jb; j0 < je; j0 += 8) {
            int j = j0 + g;
            bool act = (j < je);
            int2 cv = __ldg(&g_epk[act ? j : (je - 1)]);
            float v = act ? __int_as_float(cv.y) : 0.f;
            uint4 hq = __ldg(&tbl[(size_t)cv.x * 4 + f]);
            const __half2* hp = (const __half2*)&hq;
#pragma unroll
            for (int i = 0; i < 4; i++) {
                float2 hf = __half22float2(hp[i]);
                acc[2 * i]     += v * hf.x;
                acc[2 * i + 1] += v * hf.y;
            }
        }
        // reduce over the 8 edge subgroups (same-f lanes at xor 4,8,16)
#pragma unroll
        for (int o = 4; o <= 16; o <<= 1) {
#pragma unroll
            for (int i = 0; i < 8; i++)
                acc[i] += __shfl_xor_sync(0xffffffffu, acc[i], o);
        }
        if (g == 0) {   // lanes 0..3 write their 16B chunk
            __half2 oh[4];
#pragma unroll
            for (int i = 0; i < 4; i++)
                oh[i] = __floats2half2_rn(fmaxf(acc[2 * i], 0.f),
                                          fmaxf(acc[2 * i + 1], 0.f));
            ((uint4*)g_yh)[(size_t)r * 4 + f] = *(const uint4*)oh;
        }
        r = rn; jb = jbn; je = jen;
    }
}

// ---------------------------------------------------------------------------
// SpMM layer 2 + post-aggregation linear (segment-sum linearity):
//   aggy[r] = sum_j v_j * y[col_j] (32-dim, fp16 gathers), s[r] = sum_j v_j
//   out[r][o] = relu( aggy[r].W2[o] + s[r]*b2[o] )  -> d_out (fp32)
__global__ void spmm2_kernel(const float* __restrict__ W2,
                             const float* __restrict__ b2,
                             float* __restrict__ out_h2) {
    __shared__ float sW[HID][EMB];      // sW[k][o] = W2[o][k]
    int tid = threadIdx.x;
    for (int i = tid; i < EMB * HID; i += blockDim.x) {
        int o = i >> 5, k = i & 31;
        sW[k][o] = W2[i];
    }
    __syncthreads();

    int lane = tid & 31;
    int f = lane & 3;
    int g = lane >> 2;
    float b0 = __ldg(&b2[lane]);
    float b1 = __ldg(&b2[lane + 32]);

    int warp   = blockIdx.x * (blockDim.x >> 5) + (tid >> 5);
    int nwarps = gridDim.x * (blockDim.x >> 5);
    const uint4* tbl = (const uint4*)g_yh;

    int r = warp;
    int jb = 0, je = 0;
    if (r < NUM_NODES) { jb = __ldg(&g_row_ptr[r]); je = __ldg(&g_row_ptr[r + 1]); }
    while (r < NUM_NODES) {
        int rn = r + nwarps;
        int jbn = 0, jen = 0;
        if (rn < NUM_NODES) { jbn = __ldg(&g_row_ptr[rn]); jen = __ldg(&g_row_ptr[rn + 1]); }

        float acc[8];
#pragma unroll
        for (int i = 0; i < 8; i++) acc[i] = 0.f;
        float s = 0.f;

#pragma unroll 2
        for (int j0 = jb; j0 < je; j0 += 8) {
            int j = j0 + g;
            bool act = (j < je);
            int2 cv = __ldg(&g_epk[act ? j : (je - 1)]);
            float v = act ? __int_as_float(cv.y) : 0.f;
            uint4 hq = __ldg(&tbl[(size_t)cv.x * 4 + f]);
            const __half2* hp = (const __half2*)&hq;
#pragma unroll
            for (int i = 0; i < 4; i++) {
                float2 hf = __half22float2(hp[i]);
                acc[2 * i]     += v * hf.x;
                acc[2 * i + 1] += v * hf.y;
            }
            s += v;
        }
        // s is accumulated once per f within each g; the xor{4,8,16} tree sums
        // the 8 g-subgroups for each f-class -> each edge counted exactly once.
#pragma unroll
        for (int o = 4; o <= 16; o <<= 1) {
#pragma unroll
            for (int i = 0; i < 8; i++)
                acc[i] += __shfl_xor_sync(0xffffffffu, acc[i], o);
            s += __shfl_xor_sync(0xffffffffu, s, o);
        }
        // feature k (0..31) lives in acc[k&7] of any lane with f==k>>3;
        // use lane k>>3 (lanes 0..3) as source.
        float o0 = s * b0, o1 = s * b1;
#pragma unroll
        for (int k = 0; k < 32; k++) {
            float xk = __shfl_sync(0xffffffffu, acc[k & 7], k >> 3);
            o0 += xk * sW[k][lane];
            o1 += xk * sW[k][lane + 32];
        }
        out_h2[(size_t)r * EMB + lane]      = fmaxf(o0, 0.f);
        out_h2[(size_t)r * EMB + lane + 32] = fmaxf(o1, 0.f);
        r = rn; jb = jbn; je = jen;
    }
}

// ---------------------------------------------------------------------------
// prediction MLP. warp per batch sample; lane = hidden unit
__global__ void predict_kernel(const int* __restrict__ uid,
                               const int* __restrict__ iid,
                               const float* __restrict__ h2,
                               const float* __restrict__ p1w,
                               const float* __restrict__ p1b,
                               const float* __restrict__ p2w,
                               const float* __restrict__ p2b,
                               float* __restrict__ scores) {
    int lane = threadIdx.x & 31;
    float w[2 * EMB];
#pragma unroll
    for (int k = 0; k < 2 * EMB; k++) w[k] = __ldg(&p1w[lane * 2 * EMB + k]);
    float bias = __ldg(&p1b[lane]);
    float w2   = __ldg(&p2w[lane]);
    float b2v  = __ldg(&p2b[0]);

    int warp   = blockIdx.x * (blockDim.x >> 5) + (threadIdx.x >> 5);
    int nwarps = gridDim.x * (blockDim.x >> 5);

    for (int s = warp; s < BATCH; s += nwarps) {
        int u  = __ldg(&uid[s]);
        int it = __ldg(&iid[s]);
        const float* bu = h2 + (size_t)u * EMB;
        const float* bi = h2 + (size_t)(NUM_USERS + it) * EMB;
        float x0 = bu[lane], x1 = bu[lane + 32];
        float x2 = bi[lane], x3 = bi[lane + 32];
        float acc = bias;
#pragma unroll
        for (int k = 0; k < 32; k++) {
            acc += __shfl_sync(0xffffffffu, x0, k) * w[k];
            acc += __shfl_sync(0xffffffffu, x1, k) * w[k + 32];
            acc += __shfl_sync(0xffffffffu, x2, k) * w[k + 64];
            acc += __shfl_sync(0xffffffffu, x3, k) * w[k + 96];
        }
        float z = fmaxf(acc, 0.f) * w2;
#pragma unroll
        for (int o = 16; o > 0; o >>= 1)
            z += __shfl_xor_sync(0xffffffffu, z, o);
        if (lane == 0)
            scores[s] = 1.f / (1.f + expf(-(z + b2v)));
    }
}

// ---------------------------------------------------------------------------
extern "C" void kernel_launch(void* const* d_in, const int* in_sizes, int n_in,
                              void* d_out, int out_size) {
    const int*   user_ids = (const int*)d_in[0];
    const int*   item_ids = (const int*)d_in[1];
    const int*   adj_rows = (const int*)d_in[2];
    const int*   adj_cols = (const int*)d_in[3];
    const float* adj_vals = (const float*)d_in[4];
    const float* uemb     = (const float*)d_in[5];
    const float* iemb     = (const float*)d_in[6];
    const float* gc1w     = (const float*)d_in[7];
    const float* gc1b     = (const float*)d_in[8];
    const float* gc2w     = (const float*)d_in[9];
    const float* gc2b     = (const float*)d_in[10];
    const float* p1w      = (const float*)d_in[11];
    const float* p1b      = (const float*)d_in[12];
    const float* p2w      = (const float*)d_in[13];
    const float* p2b      = (const float*)d_in[14];

    float* out    = (float*)d_out;
    float* out_h2 = out + BATCH;   // [NUM_NODES*EMB] = concat(user_emb, item_emb)

    const int TB = 256;
    const int E4 = (N_EDGES / 4 + TB - 1) / TB;

    // 1: lin1 (fp16 table) + zero counts/tile-states
    lin1_kernel<<<592, TB>>>(uemb, iemb, gc1w, gc1b);
    // 2: degree histogram
    hist_kernel<<<E4, TB>>>(adj_rows);
    // 3: single-pass lookback scan -> row_ptr + cursor
    scan_kernel<<<NB, SCAN_BLK>>>();
    // 4: CSR permute
    permute_kernel<<<E4, TB>>>(adj_rows, adj_cols, adj_vals);
    // 5: layer-1 aggregate + ReLU (fp16 in/out, fp32 acc)
    spmm1_kernel<<<1184, TB>>>();
    // 6: layer-2 aggregate + lin2 + ReLU -> d_out (fp32)
    spmm2_kernel<<<1184, TB>>>(gc2w, gc2b, out_h2);
    // 7: prediction head
    predict_kernel<<<148, TB>>>(user_ids, item_ids, out_h2,
                                p1w, p1b, p2w, p2b, out);
}

// round 11
// speedup vs baseline: 1.0711x; 1.0337x over previous
#include <cuda_runtime.h>
#include <cuda_fp16.h>
#include <math.h>

#define NUM_USERS 60000
#define NUM_ITEMS 40000
#define NUM_NODES 100000
#define EMB 64
#define HID 32
#define N_EDGES 1600000
#define BATCH 16384

#define SCAN_BLK 1024
#define NB ((NUM_NODES + SCAN_BLK - 1) / SCAN_BLK)   // 98

#define ST_AGG  (1 << 30)
#define ST_INCL (2 << 30)
#define ST_VAL  0x3FFFFFFF

// ---------------- device scratch (allocation-free rule) ----------------
__device__ __align__(16) __half g_h1h[NUM_NODES * HID];   // lin1 out, fp16 (64B/row)
__device__ __align__(16) __half g_yh[NUM_NODES * HID];    // relu(agg1), fp16 (64B/row)
__device__ __align__(16) float  g_aggT[HID * NUM_NODES];  // layer-2 agg, TRANSPOSED [k][node]
__device__ float g_s[NUM_NODES];                          // per-row sum of vals
__device__ int   g_counts[NUM_NODES];                     // degree hist / cursor (zeroed by predict tail)
__device__ int   g_row_ptr[NUM_NODES + 1];
__device__ int   g_tile_state[NB];                        // lookback states (zeroed by predict tail)
__device__ __align__(8) int2 g_epk[N_EDGES];              // (col, val-bits), CSR order

// ---------------------------------------------------------------------------
// Fused lin1 + degree histogram. Warp-role split: first 1/4 of warps do the
// edge histogram (latency-bound, few issue slots), the rest do the lin1
// shuffle-matmul (issue-bound). g_counts arrives already zeroed (invariant).
__global__ void lin1_hist_kernel(const float* __restrict__ uemb,
                                 const float* __restrict__ iemb,
                                 const float* __restrict__ W,
                                 const float* __restrict__ b,
                                 const int* __restrict__ rows) {
    int lane = threadIdx.x & 31;
    int wid  = blockIdx.x * (blockDim.x >> 5) + (threadIdx.x >> 5);
    int nwarps = gridDim.x * (blockDim.x >> 5);
    int hist_warps = nwarps >> 2;

    if (wid < hist_warps) {
        int t = wid * 32 + lane;
        int nthr = hist_warps * 32;
        for (int e4 = t * 4; e4 < N_EDGES; e4 += nthr * 4) {
            int4 r4 = *(const int4*)(rows + e4);      // N_EDGES % 4 == 0
            atomicAdd(&g_counts[r4.x], 1);
            atomicAdd(&g_counts[r4.y], 1);
            atomicAdd(&g_counts[r4.z], 1);
            atomicAdd(&g_counts[r4.w], 1);
        }
        return;
    }

    float w[EMB];
#pragma unroll
    for (int k = 0; k < EMB; k++) w[k] = __ldg(&W[lane * EMB + k]);
    float bias = __ldg(&b[lane]);

    int wl = wid - hist_warps;
    int nl = nwarps - hist_warps;
    for (int node = wl; node < NUM_NODES; node += nl) {
        const float* feat = (node < NUM_USERS)
            ? uemb + (size_t)node * EMB
            : iemb + (size_t)(node - NUM_USERS) * EMB;
        float x0 = __ldg(&feat[lane]);
        float x1 = __ldg(&feat[lane + 32]);
        float acc = bias;
#pragma unroll
        for (int k = 0; k < 32; k++) {
            acc += __shfl_sync(0xffffffffu, x0, k) * w[k];
            acc += __shfl_sync(0xffffffffu, x1, k) * w[k + 32];
        }
        g_h1h[(size_t)node * HID + lane] = __float2half_rn(acc);
    }
}

// ---------------------------------------------------------------------------
// Single-pass exclusive scan (decoupled lookback), 98 blocks.
__global__ void scan_kernel() {
    __shared__ int sh[SCAN_BLK];
    __shared__ int s_prefix;
    int tid = threadIdx.x;
    int b = blockIdx.x;
    int i = b * SCAN_BLK + tid;
    int v = (i < NUM_NODES) ? g_counts[i] : 0;
    sh[tid] = v;
    __syncthreads();
#pragma unroll
    for (int off = 1; off < SCAN_BLK; off <<= 1) {
        int t = (tid >= off) ? sh[tid - off] : 0;
        __syncthreads();
        sh[tid] += t;
        __syncthreads();
    }
    int incl = sh[tid];
    int agg = sh[SCAN_BLK - 1];

    if (tid == 0) {
        int st = ((b == 0) ? ST_INCL : ST_AGG) | agg;
        atomicExch(&g_tile_state[b], st);
        if (b == 0) s_prefix = 0;
    }

    if (b > 0 && tid < 32) {
        int running = 0;
        int idx = b - 1;
        while (true) {
            int look = idx - tid;
            int st;
            if (look >= 0) {
                do { st = atomicAdd(&g_tile_state[look], 0); } while (st == 0);
            } else {
                st = ST_INCL;
            }
            int status = st & ~ST_VAL;
            int val    = st & ST_VAL;
            unsigned mask = __ballot_sync(0xffffffffu, status == ST_INCL);
            if (mask) {
                int first = __ffs(mask) - 1;
                int contrib = (tid <= first) ? val : 0;
#pragma unroll
                for (int o = 16; o > 0; o >>= 1)
                    contrib += __shfl_xor_sync(0xffffffffu, contrib, o);
                running += contrib;
                break;
            } else {
                int contrib = val;
#pragma unroll
                for (int o = 16; o > 0; o >>= 1)
                    contrib += __shfl_xor_sync(0xffffffffu, contrib, o);
                running += contrib;
                idx -= 32;
            }
        }
        if (tid == 0) {
            atomicExch(&g_tile_state[b], ST_INCL | (running + agg));
            s_prefix = running;
        }
    }
    __syncthreads();

    int prefix = s_prefix;
    if (i < NUM_NODES) {
        int excl = prefix + incl - v;
        g_row_ptr[i] = excl;
        g_counts[i]  = excl;          // cursor for permute
    }
    if (b == NB - 1 && tid == 0) g_row_ptr[NUM_NODES] = N_EDGES;
}

// ---------------------------------------------------------------------------
// CSR permute: 4 edges/thread
__global__ void permute_kernel(const int* __restrict__ rows,
                               const int* __restrict__ cols,
                               const float* __restrict__ vals) {
    int t = blockIdx.x * blockDim.x + threadIdx.x;
    int e4 = t * 4;
    if (e4 + 3 < N_EDGES) {
        int4   r4 = *(const int4*)(rows + e4);
        int4   c4 = *(const int4*)(cols + e4);
        float4 v4 = *(const float4*)(vals + e4);
        int p0 = atomicAdd(&g_counts[r4.x], 1);
        int p1 = atomicAdd(&g_counts[r4.y], 1);
        int p2 = atomicAdd(&g_counts[r4.z], 1);
        int p3 = atomicAdd(&g_counts[r4.w], 1);
        g_epk[p0] = make_int2(c4.x, __float_as_int(v4.x));
        g_epk[p1] = make_int2(c4.y, __float_as_int(v4.y));
        g_epk[p2] = make_int2(c4.z, __float_as_int(v4.z));
        g_epk[p3] = make_int2(c4.w, __float_as_int(v4.w));
    } else {
        for (int e = e4; e < N_EDGES; e++) {
            int pos = atomicAdd(&g_counts[rows[e]], 1);
            g_epk[pos] = make_int2(cols[e], __float_as_int(vals[e]));
        }
    }
}

// ---------------------------------------------------------------------------
// SpMM layer 1, QUAD-per-row: lane=(q,f), q=lane>>2 row subquad, f=lane&3
// 16B chunk of the 64B fp16 row. No cross-lane reduction at all.
__global__ void spmm1_kernel() {
    int lane = threadIdx.x & 31;
    int f = lane & 3;
    int q = lane >> 2;
    int warp   = blockIdx.x * (blockDim.x >> 5) + (threadIdx.x >> 5);
    int nquads = gridDim.x * (blockDim.x >> 5) * 8;
    const uint4* tbl = (const uint4*)g_h1h;

    for (int r = warp * 8 + q; r < NUM_NODES; r += nquads) {
        int jb = __ldg(&g_row_ptr[r]);
        int je = __ldg(&g_row_ptr[r + 1]);
        float acc[8];
#pragma unroll
        for (int i = 0; i < 8; i++) acc[i] = 0.f;
#pragma unroll 4
        for (int j = jb; j < je; j++) {
            int2 cv = __ldg(&g_epk[j]);              // uniform within quad
            float v = __int_as_float(cv.y);
            uint4 hq = __ldg(&tbl[(size_t)cv.x * 4 + f]);
            const __half2* hp = (const __half2*)&hq;
#pragma unroll
            for (int i = 0; i < 4; i++) {
                float2 hf = __half22float2(hp[i]);
                acc[2 * i]     += v * hf.x;
                acc[2 * i + 1] += v * hf.y;
            }
        }
        __half2 oh[4];
#pragma unroll
        for (int i = 0; i < 4; i++)
            oh[i] = __floats2half2_rn(fmaxf(acc[2 * i], 0.f),
                                      fmaxf(acc[2 * i + 1], 0.f));
        ((uint4*)g_yh)[(size_t)r * 4 + f] = *(const uint4*)oh;
    }
}

// ---------------------------------------------------------------------------
// SpMM layer 2, QUAD-per-row: aggregates y (fp16) into fp32, writes agg
// TRANSPOSED (g_aggT[k][r]) + rowsum g_s[r]. No reduction, no epilogue here.
__global__ void spmm2_kernel() {
    int lane = threadIdx.x & 31;
    int f = lane & 3;
    int q = lane >> 2;
    int warp   = blockIdx.x * (blockDim.x >> 5) + (threadIdx.x >> 5);
    int nquads = gridDim.x * (blockDim.x >> 5) * 8;
    const uint4* tbl = (const uint4*)g_yh;

    for (int r = warp * 8 + q; r < NUM_NODES; r += nquads) {
        int jb = __ldg(&g_row_ptr[r]);
        int je = __ldg(&g_row_ptr[r + 1]);
        float acc[8];
#pragma unroll
        for (int i = 0; i < 8; i++) acc[i] = 0.f;
        float s = 0.f;
#pragma unroll 4
        for (int j = jb; j < je; j++) {
            int2 cv = __ldg(&g_epk[j]);
            float v = __int_as_float(cv.y);
            uint4 hq = __ldg(&tbl[(size_t)cv.x * 4 + f]);
            const __half2* hp = (const __half2*)&hq;
#pragma unroll
            for (int i = 0; i < 4; i++) {
                float2 hf = __half22float2(hp[i]);
                acc[2 * i]     += v * hf.x;
                acc[2 * i + 1] += v * hf.y;
            }
            s += v;
        }
#pragma unroll
        for (int i = 0; i < 8; i++)
            g_aggT[(size_t)(f * 8 + i) * NUM_NODES + r] = acc[i];
        if (f == 0) g_s[r] = s;
    }
}

// ---------------------------------------------------------------------------
// lin2out: out[r][o] = relu( sum_k aggT[k][r]*W2[o][k] + s[r]*b2[o] ).
// Warp handles 8 nodes x 64 outputs; agg read as warp-uniform float4 __ldg
// (1 wavefront, L1-resident); weights in registers. Zero SHFL / LDS.
__global__ void lin2out_kernel(const float* __restrict__ W2,
                               const float* __restrict__ b2,
                               float* __restrict__ out_h2) {
    int lane = threadIdx.x & 31;
    float w0[HID], w1[HID];
#pragma unroll
    for (int k = 0; k < HID; k++) {
        w0[k] = __ldg(&W2[lane * HID + k]);
        w1[k] = __ldg(&W2[(lane + 32) * HID + k]);
    }
    float b0 = __ldg(&b2[lane]);
    float b1 = __ldg(&b2[lane + 32]);

    int warp   = blockIdx.x * (blockDim.x >> 5) + (threadIdx.x >> 5);
    int nwarps = gridDim.x * (blockDim.x >> 5);
    const int NGROUPS = NUM_NODES / 8;   // 12500 exactly

    for (int grp = warp; grp < NGROUPS; grp += nwarps) {
        int n0 = grp * 8;
        float a0[8], a1[8];   // outputs for 8 nodes: o=lane, o=lane+32
        {
            const float4* sp = (const float4*)(g_s + n0);
            float4 s01 = __ldg(&sp[0]);
            float4 s23 = __ldg(&sp[1]);
            a0[0] = s01.x * b0; a1[0] = s01.x * b1;
            a0[1] = s01.y * b0; a1[1] = s01.y * b1;
            a0[2] = s01.z * b0; a1[2] = s01.z * b1;
            a0[3] = s01.w * b0; a1[3] = s01.w * b1;
            a0[4] = s23.x * b0; a1[4] = s23.x * b1;
            a0[5] = s23.y * b0; a1[5] = s23.y * b1;
            a0[6] = s23.z * b0; a1[6] = s23.z * b1;
            a0[7] = s23.w * b0; a1[7] = s23.w * b1;
        }
#pragma unroll
        for (int k = 0; k < HID; k++) {
            const float4* ap = (const float4*)(g_aggT + (size_t)k * NUM_NODES + n0);
            float4 x03 = __ldg(&ap[0]);          // warp-uniform broadcast
            float4 x47 = __ldg(&ap[1]);
            a0[0] += x03.x * w0[k]; a1[0] += x03.x * w1[k];
            a0[1] += x03.y * w0[k]; a1[1] += x03.y * w1[k];
            a0[2] += x03.z * w0[k]; a1[2] += x03.z * w1[k];
            a0[3] += x03.w * w0[k]; a1[3] += x03.w * w1[k];
            a0[4] += x47.x * w0[k]; a1[4] += x47.x * w1[k];
            a0[5] += x47.y * w0[k]; a1[5] += x47.y * w1[k];
            a0[6] += x47.z * w0[k]; a1[6] += x47.z * w1[k];
            a0[7] += x47.w * w0[k]; a1[7] += x47.w * w1[k];
        }
#pragma unroll
        for (int n = 0; n < 8; n++) {
            out_h2[(size_t)(n0 + n) * EMB + lane]      = fmaxf(a0[n], 0.f);
            out_h2[(size_t)(n0 + n) * EMB + lane + 32] = fmaxf(a1[n], 0.f);
        }
    }
}

// ---------------------------------------------------------------------------
// prediction MLP + state cleanup (restores the zeroed-counts invariant).
__global__ void predict_kernel(const int* __restrict__ uid,
                               const int* __restrict__ iid,
                               const float* __restrict__ h2,
                               const float* __restrict__ p1w,
                               const float* __restrict__ p1b,
                               const float* __restrict__ p2w,
                               const float* __restrict__ p2b,
                               float* __restrict__ scores) {
    // cleanup: zero cursor/state arrays for the next execution (rotation invariant)
    int gt = blockIdx.x * blockDim.x + threadIdx.x;
    int nthr = gridDim.x * blockDim.x;
    for (int i = gt; i < NUM_NODES; i += nthr) g_counts[i] = 0;
    if (gt < NB) g_tile_state[gt] = 0;

    int lane = threadIdx.x & 31;
    float w[2 * EMB];
#pragma unroll
    for (int k = 0; k < 2 * EMB; k++) w[k] = __ldg(&p1w[lane * 2 * EMB + k]);
    float bias = __ldg(&p1b[lane]);
    float w2   = __ldg(&p2w[lane]);
    float b2v  = __ldg(&p2b[0]);

    int warp   = blockIdx.x * (blockDim.x >> 5) + (threadIdx.x >> 5);
    int nwarps = gridDim.x * (blockDim.x >> 5);

    for (int s = warp; s < BATCH; s += nwarps) {
        int u  = __ldg(&uid[s]);
        int it = __ldg(&iid[s]);
        const float* bu = h2 + (size_t)u * EMB;
        const float* bi = h2 + (size_t)(NUM_USERS + it) * EMB;
        float x0 = bu[lane], x1 = bu[lane + 32];
        float x2 = bi[lane], x3 = bi[lane + 32];
        float acc = bias;
#pragma unroll
        for (int k = 0; k < 32; k++) {
            acc += __shfl_sync(0xffffffffu, x0, k) * w[k];
            acc += __shfl_sync(0xffffffffu, x1, k) * w[k + 32];
            acc += __shfl_sync(0xffffffffu, x2, k) * w[k + 64];
            acc += __shfl_sync(0xffffffffu, x3, k) * w[k + 96];
        }
        float z = fmaxf(acc, 0.f) * w2;
#pragma unroll
        for (int o = 16; o > 0; o >>= 1)
            z += __shfl_xor_sync(0xffffffffu, z, o);
        if (lane == 0)
            scores[s] = 1.f / (1.f + expf(-(z + b2v)));
    }
}

// ---------------------------------------------------------------------------
extern "C" void kernel_launch(void* const* d_in, const int* in_sizes, int n_in,
                              void* d_out, int out_size) {
    const int*   user_ids = (const int*)d_in[0];
    const int*   item_ids = (const int*)d_in[1];
    const int*   adj_rows = (const int*)d_in[2];
    const int*   adj_cols = (const int*)d_in[3];
    const float* adj_vals = (const float*)d_in[4];
    const float* uemb     = (const float*)d_in[5];
    const float* iemb     = (const float*)d_in[6];
    const float* gc1w     = (const float*)d_in[7];
    const float* gc1b     = (const float*)d_in[8];
    const float* gc2w     = (const float*)d_in[9];
    const float* gc2b     = (const float*)d_in[10];
    const float* p1w      = (const float*)d_in[11];
    const float* p1b      = (const float*)d_in[12];
    const float* p2w      = (const float*)d_in[13];
    const float* p2b      = (const float*)d_in[14];

    float* out    = (float*)d_out;
    float* out_h2 = out + BATCH;   // [NUM_NODES*EMB] = concat(user_emb, item_emb)

    const int TB = 256;
    const int E4 = (N_EDGES / 4 + TB - 1) / TB;

    // 1: fused lin1 (fp16 table) + degree histogram (counts pre-zeroed invariant)
    lin1_hist_kernel<<<592, TB>>>(uemb, iemb, gc1w, gc1b, adj_rows);
    // 2: single-pass lookback scan -> row_ptr + cursor
    scan_kernel<<<NB, SCAN_BLK>>>();
    // 3: CSR permute
    permute_kernel<<<E4, TB>>>(adj_rows, adj_cols, adj_vals);
    // 4: layer-1 aggregate + ReLU (quad-per-row, no shuffles)
    spmm1_kernel<<<1184, TB>>>();
    // 5: layer-2 aggregate -> transposed agg + rowsum (quad-per-row)
    spmm2_kernel<<<1184, TB>>>();
    // 6: dense lin2 + bias + ReLU -> d_out embeddings
    lin2out_kernel<<<1184, TB>>>(gc2w, gc2b, out_h2);
    // 7: prediction head + state cleanup
    predict_kernel<<<148, TB>>>(user_ids, item_ids, out_h2,
                                p1w, p1b, p2w, p2b, out);
}